// round 16
// baseline (speedup 1.0000x reference)
#include <cuda_runtime.h>
#include <math.h>

#define HH  192
#define NPX 36864
#define NB  4
#define NCH 192
#define QW  96
#define NQ  9216          // 96*96 quadrant pixels
#define NT  1152          // stats tiles: 4 batches * 288 pixel-blocks (128 px each)
#define NTILE 136         // upper-triangular 4x4 tiles of 16x16 tile grid
#define GPW 2240          // 136*16 Gram entries + 64 S entries

__device__ float2 d_Wf[HH*HH];
__device__ float2 d_Wb[HH*HH];
__device__ float2 d_Y[12][NPX];         // row-pass temp (6 used, packed)
__device__ float2 d_Z[6][NPX];          // packed spectra
__device__ float2 d_F[12][NPX];
__device__ float  d_h2q[NB*NQ*NCH];
__device__ float  d_gpart[NT][GPW];
__device__ double d_gmid[36][GPW];
__device__ double d_Gd[NTILE*16];
__device__ double d_Sd[64];
__device__ float  d_bnA[NCH], d_bnB[NCH];
__device__ float2 d_A[NQ];
__device__ float2 d_T[64][QW*HH];
__device__ float  d_xf[64*NPX];
__device__ float4 d_soiA[576];
__device__ float2 d_soiB[576];
__device__ int    d_band[192*2];
__device__ int2   d_obox[64];
__device__ float  d_pix[3][NPX];

// ---- FMA-poly transcendentals ----
__device__ __forceinline__ float fexp(float x) {
    if (!(x > -87.33654f)) return 0.0f;
    float y = x * 1.4426950408889634f;
    float n = rintf(y);
    float f = y - n;
    float p = 1.5403530e-4f;
    p = fmaf(p, f, 1.3333558e-3f);
    p = fmaf(p, f, 9.6181291e-3f);
    p = fmaf(p, f, 5.5504109e-2f);
    p = fmaf(p, f, 2.4022651e-1f);
    p = fmaf(p, f, 6.9314718e-1f);
    p = fmaf(p, f, 1.0f);
    return __int_as_float(((int)n + 127) << 23) * p;
}
__device__ __forceinline__ float fcos(float x) {   // |x| < ~6
    float qf = rintf(x * 0.6366197723675814f);
    int   q  = (int)qf;
    float t  = fmaf(qf, -1.5707963705062866f, x);
    t = fmaf(qf, 4.3711388e-8f, t);
    float s = t * t;
    float c = fmaf(s, fmaf(s, fmaf(s, 2.4433157e-5f, -1.3887316e-3f), 4.1666646e-2f), -0.5f);
    c = fmaf(c, s, 1.0f);
    float sn = t * fmaf(s, fmaf(s, fmaf(s, -1.9515296e-4f, 8.3321609e-3f), -1.6666655e-1f), 1.0f);
    int qm = q & 3;
    return (qm == 0) ? c : (qm == 1) ? -sn : (qm == 2) ? -c : sn;
}

// ---- fused init ----
__global__ void k_init(const float* freq, const float* theta, const float* sigma,
                       const float* f0, const float* theta0, const float* fbs) {
    int idx = blockIdx.x * blockDim.x + threadIdx.x;
    if (idx >= NPX) return;
    {
        int k = idx / HH, n = idx % HH;
        int m = (k * n) % HH;
        float s, c;
        sincospif((float)m / 96.0f, &s, &c);
        d_Wf[idx] = make_float2(c, -s);
        d_Wb[idx] = make_float2(c * (1.0f / 192.0f), s * (1.0f / 192.0f));
    }
    {
        int u = idx / HH, v = idx % HH;
        int hs = (u >= 96) ? u - 96 : u + 96;
        int ws = (v >= 96) ? v - 96 : v + 96;
        float yy = -1.0f + hs * (2.0f / 191.0f);
        float xx = -1.0f + ws * (2.0f / 191.0f);
        float r  = sqrtf(xx * xx + yy * yy + 1e-6f);
        d_pix[0][idx] = logf(r);
        d_pix[1][idx] = atan2f(yy, xx);
        d_pix[2][idx] = r;
    }
    if (idx < 576) {
        float sg = sigma[idx], f0v = f0[idx], t0 = theta0[idx];
        float lf0 = logf(f0v);
        float dl  = logf(sg) - lf0;
        d_soiA[idx] = make_float4(lf0, 0.5f / (dl * dl), theta[idx], 0.5f / (t0 * t0));
        d_soiB[idx] = make_float2(freq[idx], 1.0f / (6.283185307179586f * sg * sg));
    }
    if (idx < 192) {
        d_band[idx * 2 + 0] = (int)floorf((fbs[idx * 2 + 0] + 1.0f) * 0.5f * 192.0f);
        d_band[idx * 2 + 1] = (int)floorf((fbs[idx * 2 + 1] + 1.0f) * 0.5f * 192.0f);
    }
}

// ---- per-channel union bounding box (quadrant coords) ----
__global__ void k_box() {
    int o = threadIdx.x;            // 64 threads
    int os = (o + 32) & 63;
    int bmin = QW, bmax = 0;
    for (int i = 0; i < 3; i++) {
        int lo = d_band[(os * 3 + i) * 2] - 96;
        int hi = d_band[(os * 3 + i) * 2 + 1] - 96;
        if (lo < 0) lo = 0;
        if (hi > lo) { bmin = min(bmin, lo); bmax = max(bmax, hi); }
    }
    if (bmax <= bmin) { bmin = 0; bmax = 0; }
    d_obox[o] = make_int2(bmin, bmax);
}

// ---- forward DFT rows: Hermitian-packed pairs, R=2 for occupancy ----
__global__ __launch_bounds__(192) void k_fwd_rows(const float* x) {
    int k = blockIdx.x, h0 = blockIdx.y * 2, tid = threadIdx.x;
    __shared__ float2 xs[2][HH];
    const float* xa = x + (2 * k)     * NPX;
    const float* xb = x + (2 * k + 1) * NPX;
    for (int j = tid; j < 2 * HH; j += 192) {
        int idx = (h0 + j / HH) * HH + (j % HH);
        xs[j / HH][j % HH] = make_float2(xa[idx], xb[idx]);
    }
    __syncthreads();
    float ar[2], ai[2];
    #pragma unroll
    for (int r = 0; r < 2; r++) { ar[r] = 0.0f; ai[r] = 0.0f; }
    #pragma unroll 8
    for (int w = 0; w < HH; w++) {
        float2 W = d_Wf[w * HH + tid];
        #pragma unroll
        for (int r = 0; r < 2; r++) {
            float2 xv = xs[r][w];
            ar[r] = fmaf(xv.x, W.x, fmaf(-xv.y, W.y, ar[r]));
            ai[r] = fmaf(xv.x, W.y, fmaf( xv.y, W.x, ai[r]));
        }
    }
    #pragma unroll
    for (int r = 0; r < 2; r++)
        d_Y[k][(h0 + r) * HH + tid] = make_float2(ar[r], ai[r]);
}

// ---- forward DFT cols: 6 packed transforms, R=2 ----
__global__ __launch_bounds__(192) void k_fwd_cols() {
    int k = blockIdx.x, u0 = blockIdx.y * 2, tid = threadIdx.x;
    __shared__ float2 wt[2][HH];
    for (int j = tid; j < 2 * HH; j += 192)
        wt[j / HH][j % HH] = d_Wf[(u0 + j / HH) * HH + (j % HH)];
    __syncthreads();
    float fr[2], fi[2];
    #pragma unroll
    for (int r = 0; r < 2; r++) { fr[r] = 0.0f; fi[r] = 0.0f; }
    #pragma unroll 8
    for (int h = 0; h < HH; h++) {
        float2 y = d_Y[k][h * HH + tid];
        #pragma unroll
        for (int r = 0; r < 2; r++) {
            float2 w = wt[r][h];
            fr[r] = fmaf(w.x, y.x, fmaf(-w.y, y.y, fr[r]));
            fi[r] = fmaf(w.x, y.y, fmaf( w.y, y.x, fi[r]));
        }
    }
    #pragma unroll
    for (int r = 0; r < 2; r++)
        d_Z[k][(u0 + r) * HH + tid] = make_float2(fr[r], fi[r]);
}

// ---- Hermitian unpack: Z[k] -> F[2k], F[2k+1] ----
__global__ __launch_bounds__(256) void k_unpack() {
    int px = blockIdx.x * 256 + threadIdx.x;
    if (px >= NPX) return;
    int k = blockIdx.y;
    int u = px / HH, v = px % HH;
    int mu = (HH - u) % HH, mv = (HH - v) % HH;
    float2 Z  = d_Z[k][px];
    float2 Zm = d_Z[k][mu * HH + mv];
    d_F[2 * k    ][px] = make_float2(0.5f * (Z.x + Zm.x), 0.5f * (Z.y - Zm.y));
    d_F[2 * k + 1][px] = make_float2(0.5f * (Z.y + Zm.y), 0.5f * (Zm.x - Z.x));
}

// ---- attention stats: 128-px tiles, pixel-major h1, float4 Gram ----
__global__ __launch_bounds__(192) void k_attn_stats(const float* w1, const float* b1) {
    int b = blockIdx.x, py = blockIdx.y, px0 = py * 128, tid = threadIdx.x;
    __shared__ float mags[3][128];
    __shared__ __align__(16) float h1t[128][64];   // pixel-major
    for (int jj = tid; jj < 384; jj += 192) {
        int c = jj >> 7, p = jj & 127;
        int ip = (c == 0) ? 2 : (c - 1);           // channel fftshift perm
        float2 F = d_F[b * 3 + ip][px0 + p];
        mags[c][p] = sqrtf(F.x * F.x + F.y * F.y);
    }
    int hid = tid & 63, grp = tid >> 6;
    float w1a = w1[hid * 3], w1b = w1[hid * 3 + 1], w1c = w1[hid * 3 + 2], b1v = b1[hid];
    __syncthreads();
    for (int p = grp; p < 128; p += 3)
        h1t[p][hid] = fmaxf(fmaf(w1a, mags[0][p],
                       fmaf(w1b, mags[1][p], fmaf(w1c, mags[2][p], b1v))), 0.0f);
    __syncthreads();
    int blk = b * 288 + py;
    if (tid < 64) {
        float s = 0.0f;
        #pragma unroll 8
        for (int p = 0; p < 128; p++) s += h1t[p][tid];
        d_gpart[blk][NTILE * 16 + tid] = s;
    }
    if (tid < NTILE) {
        int J = 0, rem = tid;
        while (rem >= 16 - J) { rem -= 16 - J; J++; }
        int K = J + rem;
        float acc[4][4];
        #pragma unroll
        for (int a = 0; a < 4; a++)
            #pragma unroll
            for (int c = 0; c < 4; c++) acc[a][c] = 0.0f;
        #pragma unroll 4
        for (int p = 0; p < 128; p++) {
            float4 ra = *(const float4*)&h1t[p][J * 4];
            float4 rb = *(const float4*)&h1t[p][K * 4];
            acc[0][0] = fmaf(ra.x, rb.x, acc[0][0]);
            acc[0][1] = fmaf(ra.x, rb.y, acc[0][1]);
            acc[0][2] = fmaf(ra.x, rb.z, acc[0][2]);
            acc[0][3] = fmaf(ra.x, rb.w, acc[0][3]);
            acc[1][0] = fmaf(ra.y, rb.x, acc[1][0]);
            acc[1][1] = fmaf(ra.y, rb.y, acc[1][1]);
            acc[1][2] = fmaf(ra.y, rb.z, acc[1][2]);
            acc[1][3] = fmaf(ra.y, rb.w, acc[1][3]);
            acc[2][0] = fmaf(ra.z, rb.x, acc[2][0]);
            acc[2][1] = fmaf(ra.z, rb.y, acc[2][1]);
            acc[2][2] = fmaf(ra.z, rb.z, acc[2][2]);
            acc[2][3] = fmaf(ra.z, rb.w, acc[2][3]);
            acc[3][0] = fmaf(ra.w, rb.x, acc[3][0]);
            acc[3][1] = fmaf(ra.w, rb.y, acc[3][1]);
            acc[3][2] = fmaf(ra.w, rb.z, acc[3][2]);
            acc[3][3] = fmaf(ra.w, rb.w, acc[3][3]);
        }
        #pragma unroll
        for (int a = 0; a < 4; a++)
            #pragma unroll
            for (int c = 0; c < 4; c++)
                d_gpart[blk][tid * 16 + a * 4 + c] = acc[a][c];
    }
}

// ---- attention h2: 128-px quadrant tiles, padded h1 ----
__global__ __launch_bounds__(192) void k_attn_h2(const float* w1, const float* b1,
                                                 const float* w2, const float* b2) {
    int b = blockIdx.x, q0 = blockIdx.y * 128, tid = threadIdx.x;
    __shared__ float mags[3][128];
    __shared__ __align__(16) float h1s[64][132];   // hid-major, pad 132
    for (int jj = tid; jj < 384; jj += 192) {
        int c = jj >> 7, p = jj & 127;
        int q = q0 + p;
        int px = (q / QW) * HH + (q % QW);
        int ip = (c == 0) ? 2 : (c - 1);
        float2 F = d_F[b * 3 + ip][px];
        mags[c][p] = sqrtf(F.x * F.x + F.y * F.y);
    }
    int hid = tid & 63, grp = tid >> 6;
    float w1a = w1[hid * 3], w1b = w1[hid * 3 + 1], w1c = w1[hid * 3 + 2], b1v = b1[hid];
    __syncthreads();
    for (int p = grp; p < 128; p += 3)
        h1s[hid][p] = fmaxf(fmaf(w1a, mags[0][p],
                       fmaf(w1b, mags[1][p], fmaf(w1c, mags[2][p], b1v))), 0.0f);
    float w2row[64];
    #pragma unroll
    for (int j = 0; j < 64; j++) w2row[j] = w2[tid * 64 + j];
    float bias2 = b2[tid];
    __syncthreads();
    for (int g = 0; g < 32; g++) {
        float a0 = bias2, a1 = bias2, a2 = bias2, a3 = bias2;
        #pragma unroll
        for (int j = 0; j < 64; j++) {
            float4 h = *(const float4*)&h1s[j][g * 4];
            float wv = w2row[j];
            a0 = fmaf(wv, h.x, a0); a1 = fmaf(wv, h.y, a1);
            a2 = fmaf(wv, h.z, a2); a3 = fmaf(wv, h.w, a3);
        }
        long base = ((long)b * NQ + q0 + g * 4) * NCH + tid;
        d_h2q[base          ] = a0;
        d_h2q[base + NCH    ] = a1;
        d_h2q[base + 2 * NCH] = a2;
        d_h2q[base + 3 * NCH] = a3;
    }
}

// ---- Gram/S reduction ----
__global__ __launch_bounds__(256) void k_gred1() {
    int m = blockIdx.x;
    for (int e = threadIdx.x; e < GPW; e += 256) {
        double s = 0.0;
        for (int blk = m * 32; blk < m * 32 + 32; blk++)
            s += (double)d_gpart[blk][e];
        d_gmid[m][e] = s;
    }
}
__global__ __launch_bounds__(256) void k_gred2() {
    for (int e = threadIdx.x; e < GPW; e += 256) {
        double s = 0.0;
        for (int m = 0; m < 36; m++) s += d_gmid[m][e];
        if (e < NTILE * 16) d_Gd[e] = s;
        else d_Sd[e - NTILE * 16] = s;
    }
}

// ---- BN finalize via quadratic form ----
__global__ __launch_bounds__(64) void k_bnfin(const float* w2, const float* b2,
                                              const float* bnw, const float* bnb) {
    int c = blockIdx.x, j = threadIdx.x;
    __shared__ float w2s[64];
    __shared__ double sh1[64], sh2[64];
    w2s[j] = w2[c * 64 + j];
    __syncthreads();
    double wj = (double)w2s[j];
    double rowsum = 0.0;
    for (int k = 0; k < 64; k++) {
        int J = j >> 2, K = k >> 2, rj = j & 3, rk = k & 3;
        int off;
        if (J <= K) off = (J * 16 - (J * (J - 1)) / 2 + (K - J)) * 16 + rj * 4 + rk;
        else        off = (K * 16 - (K * (K - 1)) / 2 + (J - K)) * 16 + rk * 4 + rj;
        rowsum += d_Gd[off] * (double)w2s[k];
    }
    sh1[j] = wj * rowsum;
    sh2[j] = wj * d_Sd[j];
    __syncthreads();
    if (j == 0) {
        double quad = 0.0, ws = 0.0;
        for (int k = 0; k < 64; k++) { quad += sh1[k]; ws += sh2[k]; }
        double N   = (double)((long)NB * NPX);
        double b2c = (double)b2[c];
        double mu  = (ws + N * b2c) / N;
        double msq = (quad + 2.0 * b2c * ws + N * b2c * b2c) / N;
        double var = msq - mu * mu;
        float inv  = (float)(1.0 / sqrt(var + 1e-5));
        float A    = inv * bnw[c];
        d_bnA[c] = A;
        d_bnB[c] = bnb[c] - (float)mu * A;
    }
}

// ---- fused BN + softmax + gabor + A_tot: warp-per-pixel ----
__global__ __launch_bounds__(192) void k_atot() {
    int wid = threadIdx.x >> 5, lane = threadIdx.x & 31;
    int q = blockIdx.x * 6 + wid;
    int u = q / QW, v = q % QW;
    int px = u * HH + v;
    float2 Fv = make_float2(0.0f, 0.0f);
    if (lane < 12) {
        int b = lane / 3, i = lane % 3;
        int ip = (i == 0) ? 2 : (i - 1);
        Fv = d_F[b * 3 + ip][px];
    }
    float pv = (lane < 3) ? d_pix[lane][px] : 0.0f;
    float L   = __shfl_sync(0xffffffffu, pv, 0);
    float phi = __shfl_sync(0xffffffffu, pv, 1);
    float rr  = __shfl_sync(0xffffffffu, pv, 2);
    float Xr[4][3], Xi[4][3];
    #pragma unroll
    for (int b = 0; b < 4; b++)
        #pragma unroll
        for (int i = 0; i < 3; i++) {
            Xr[b][i] = __shfl_sync(0xffffffffu, Fv.x, b * 3 + i);
            Xi[b][i] = __shfl_sync(0xffffffffu, Fv.y, b * 3 + i);
        }
    float bnA[6], bnB[6];
    #pragma unroll
    for (int k = 0; k < 6; k++) {
        bnA[k] = d_bnA[lane + 32 * k];
        bnB[k] = d_bnB[lane + 32 * k];
    }
    float e[4][6], ssum[4];
    #pragma unroll
    for (int b = 0; b < 4; b++) {
        long base = ((long)b * NQ + q) * NCH + lane;
        float ls = 0.0f;
        #pragma unroll
        for (int k = 0; k < 6; k++) {
            e[b][k] = fexp(fmaf(d_h2q[base + 32 * k], bnA[k], bnB[k]));
            ls += e[b][k];
        }
        #pragma unroll
        for (int o = 16; o > 0; o >>= 1) ls += __shfl_xor_sync(0xffffffffu, ls, o);
        ssum[b] = ls;
    }
    float i0 = 1.0f / ssum[0], i1 = 1.0f / ssum[1], i2 = 1.0f / ssum[2], i3 = 1.0f / ssum[3];
    float accr = 0.0f, acci = 0.0f;
    #pragma unroll
    for (int k = 0; k < 6; k++) {
        int c = lane + 32 * k;
        float w0 = e[0][k] * i0, w1 = e[1][k] * i1, w2v = e[2][k] * i2, w3 = e[3][k] * i3;
        #pragma unroll
        for (int i = 0; i < 3; i++) {
            float ar = w0 * Xr[0][i] + w1 * Xr[1][i] + w2v * Xr[2][i] + w3 * Xr[3][i];
            float ai = w0 * Xi[0][i] + w1 * Xi[1][i] + w2v * Xi[2][i] + w3 * Xi[3][i];
            float4 pa = d_soiA[c * 3 + i];
            float2 pb = d_soiB[c * 3 + i];
            float dl = L - pa.x;
            float dp = phi - pa.z;
            float g = fexp(-(dl * dl) * pa.y - (dp * dp) * pa.w) * fcos(pb.x * rr) * pb.y;
            accr = fmaf(g, ar, accr);
            acci = fmaf(g, ai, acci);
        }
    }
    #pragma unroll
    for (int o = 16; o > 0; o >>= 1) {
        accr += __shfl_xor_sync(0xffffffffu, accr, o);
        acci += __shfl_xor_sync(0xffffffffu, acci, o);
    }
    if (lane == 0) d_A[q] = make_float2(accr, acci);
}

// ---- inverse DFT rows: R=12, static loops; zero-fill strips outside box ----
__global__ __launch_bounds__(192) void k_inv_rows() {
    int o = blockIdx.x, u0 = blockIdx.y * 12, tid = threadIdx.x;
    int2 box = d_obox[o];
    if (u0 >= box.y || u0 + 12 <= box.x) {
        float2 z = make_float2(0.0f, 0.0f);
        #pragma unroll
        for (int r = 0; r < 12; r++)
            d_T[o][(u0 + r) * HH + tid] = z;
        return;
    }
    int os = (o + 32) & 63;
    int lo0 = d_band[(os * 3 + 0) * 2] - 96, hi0 = d_band[(os * 3 + 0) * 2 + 1] - 96;
    int lo1 = d_band[(os * 3 + 1) * 2] - 96, hi1 = d_band[(os * 3 + 1) * 2 + 1] - 96;
    int lo2 = d_band[(os * 3 + 2) * 2] - 96, hi2 = d_band[(os * 3 + 2) * 2 + 1] - 96;
    __shared__ float2 qs[12][QW];
    for (int j = tid; j < 12 * QW; j += 192) {
        int r = j / QW, v = j % QW;
        int u = u0 + r;
        bool a0 = (u >= lo0) && (u < hi0), b0 = (v >= lo0) && (v < hi0);
        bool a1 = (u >= lo1) && (u < hi1), b1 = (v >= lo1) && (v < hi1);
        bool a2 = (u >= lo2) && (u < hi2), b2 = (v >= lo2) && (v < hi2);
        float m = (float)((a0 & b0) + (a1 & b1) + (a2 & b2));
        float2 a = d_A[u * QW + v];
        qs[r][v] = make_float2(a.x * m, a.y * m);
    }
    __syncthreads();
    float tr[12], ti[12];
    #pragma unroll
    for (int r = 0; r < 12; r++) { tr[r] = 0.0f; ti[r] = 0.0f; }
    #pragma unroll 8
    for (int v = 0; v < QW; v++) {
        float2 w = d_Wb[v * HH + tid];
        #pragma unroll
        for (int r = 0; r < 12; r++) {
            float2 qv = qs[r][v];
            tr[r] = fmaf(qv.x, w.x, fmaf(-qv.y, w.y, tr[r]));
            ti[r] = fmaf(qv.x, w.y, fmaf( qv.y, w.x, ti[r]));
        }
    }
    #pragma unroll
    for (int r = 0; r < 12; r++)
        d_T[o][(u0 + r) * HH + tid] = make_float2(tr[r], ti[r]);
}

// ---- inverse DFT cols (real part), R=12 ----
__global__ __launch_bounds__(192) void k_inv_cols() {
    int o = blockIdx.x, s0 = blockIdx.y * 12, tid = threadIdx.x;
    __shared__ float2 wt[12][QW];
    for (int j = tid; j < 12 * QW; j += 192) {
        int r = j / QW, u = j % QW;
        wt[r][u] = d_Wb[(s0 + r) * HH + u];
    }
    __syncthreads();
    float acc[12];
    #pragma unroll
    for (int r = 0; r < 12; r++) acc[r] = 0.0f;
    #pragma unroll 8
    for (int u = 0; u < QW; u++) {
        float2 t = d_T[o][u * HH + tid];
        #pragma unroll
        for (int r = 0; r < 12; r++) {
            float2 w = wt[r][u];
            acc[r] = fmaf(w.x, t.x, fmaf(-w.y, t.y, acc[r]));
        }
    }
    #pragma unroll
    for (int r = 0; r < 12; r++)
        d_xf[o * NPX + (s0 + r) * HH + tid] = acc[r];
}

// ---- 3x3 conv + mixing: padded float4 weights ----
__global__ __launch_bounds__(256) void k_conv(const float* x, const float* cw,
                                              const float* mp, float* out) {
    int b = blockIdx.z;
    int h0 = blockIdx.y * 16, w0 = blockIdx.x * 16;
    int tx = threadIdx.x, ty = threadIdx.y;
    int t = ty * 16 + tx;
    __shared__ float xt[3][18][18];
    __shared__ __align__(16) float cws[64 * 28];
    for (int j = t; j < 972; j += 256) {
        int i = j / 324, rem = j % 324, hh = rem / 18, ww = rem % 18;
        int gh = h0 - 1 + hh, gw = w0 - 1 + ww;
        xt[i][hh][ww] = (gh >= 0 && gh < HH && gw >= 0 && gw < HH)
                        ? x[(b * 3 + i) * NPX + gh * HH + gw] : 0.0f;
    }
    for (int j = t; j < 1728; j += 256) cws[(j / 27) * 28 + (j % 27)] = cw[j];
    for (int j = t; j < 64; j += 256) cws[j * 28 + 27] = 0.0f;
    __syncthreads();
    float mix = mp[0];
    float win[28];
    #pragma unroll
    for (int i = 0; i < 3; i++)
        #pragma unroll
        for (int kh = 0; kh < 3; kh++)
            #pragma unroll
            for (int kw = 0; kw < 3; kw++)
                win[i * 9 + kh * 3 + kw] = xt[i][ty + kh][tx + kw];
    win[27] = 0.0f;
    int pix = (h0 + ty) * HH + (w0 + tx);
    for (int o = 0; o < 64; o++) {
        float acc = 0.0f;
        #pragma unroll
        for (int g = 0; g < 7; g++) {
            float4 cv = *(const float4*)&cws[o * 28 + g * 4];
            acc = fmaf(win[g*4+0], cv.x, acc);
            acc = fmaf(win[g*4+1], cv.y, acc);
            acc = fmaf(win[g*4+2], cv.z, acc);
            acc = fmaf(win[g*4+3], cv.w, acc);
        }
        out[((b * 64 + o) * NPX) + pix] = fmaf(mix, d_xf[o * NPX + pix], (1.0f - mix) * acc);
    }
}

extern "C" void kernel_launch(void* const* d_in, const int* in_sizes, int n_in,
                              void* d_out, int out_size) {
    const float* x    = (const float*)d_in[0];
    const float* freq = (const float*)d_in[1];
    const float* thet = (const float*)d_in[2];
    const float* sigm = (const float*)d_in[3];
    const float* f0   = (const float*)d_in[4];
    const float* th0  = (const float*)d_in[5];
    const float* w1   = (const float*)d_in[6];
    const float* b1   = (const float*)d_in[7];
    const float* w2   = (const float*)d_in[8];
    const float* b2   = (const float*)d_in[9];
    const float* bnw  = (const float*)d_in[10];
    const float* bnb  = (const float*)d_in[11];
    const float* mp   = (const float*)d_in[12];
    const float* cw   = (const float*)d_in[13];
    const float* fbs  = (const float*)d_in[14];
    float* out = (float*)d_out;

    k_init<<<144, 256>>>(freq, thet, sigm, f0, th0, fbs);
    k_box<<<1, 64>>>();
    k_fwd_rows<<<dim3(6, 96), 192>>>(x);
    k_fwd_cols<<<dim3(6, 96), 192>>>();
    k_unpack<<<dim3(144, 6), 256>>>();
    k_attn_stats<<<dim3(4, 288), 192>>>(w1, b1);
    k_attn_h2<<<dim3(4, 72), 192>>>(w1, b1, w2, b2);
    k_gred1<<<36, 256>>>();
    k_gred2<<<1, 256>>>();
    k_bnfin<<<192, 64>>>(w2, b2, bnw, bnb);
    k_atot<<<1536, 192>>>();
    k_inv_rows<<<dim3(64, 8), 192>>>();
    k_inv_cols<<<dim3(64, 16), 192>>>();
    k_conv<<<dim3(12, 12, 4), dim3(16, 16)>>>(x, cw, mp, out);
}

// round 17
// speedup vs baseline: 1.5302x; 1.5302x over previous
#include <cuda_runtime.h>
#include <math.h>

#define HH  192
#define NPX 36864
#define NB  4
#define NCH 192
#define QW  96
#define NQ  9216          // 96*96 quadrant pixels
#define NT  1152          // stats tiles: 4 batches * 288 pixel-blocks (128 px each)
#define NTILE 136         // upper-triangular 4x4 tiles of 16x16 tile grid
#define GPW 2240          // 136*16 Gram entries + 64 S entries

__device__ float2 d_Wf[HH*HH];
__device__ float2 d_Wb[HH*HH];
__device__ float2 d_Y[12][NPX];         // row-pass temp (6 used, packed)
__device__ float2 d_Z[6][NPX];          // packed spectra
__device__ float2 d_F[12][NPX];
__device__ float  d_h2q[NB*NQ*NCH];
__device__ float  d_gpart[NT][GPW];
__device__ double d_gmid[36][GPW];
__device__ double d_Gd[NTILE*16];
__device__ double d_Sd[64];
__device__ float  d_bnA[NCH], d_bnB[NCH];
__device__ float2 d_A[NQ];
__device__ float2 d_T[64][QW*HH];
__device__ float  d_xf[64*NPX];
__device__ float4 d_soiA[576];
__device__ float2 d_soiB[576];
__device__ int    d_band[192*2];
__device__ int2   d_obox[64];
__device__ float  d_pix[3][NPX];

// ---- FMA-poly transcendentals ----
__device__ __forceinline__ float fexp(float x) {
    if (!(x > -87.33654f)) return 0.0f;
    float y = x * 1.4426950408889634f;
    float n = rintf(y);
    float f = y - n;
    float p = 1.5403530e-4f;
    p = fmaf(p, f, 1.3333558e-3f);
    p = fmaf(p, f, 9.6181291e-3f);
    p = fmaf(p, f, 5.5504109e-2f);
    p = fmaf(p, f, 2.4022651e-1f);
    p = fmaf(p, f, 6.9314718e-1f);
    p = fmaf(p, f, 1.0f);
    return __int_as_float(((int)n + 127) << 23) * p;
}
__device__ __forceinline__ float fcos(float x) {   // |x| < ~6
    float qf = rintf(x * 0.6366197723675814f);
    int   q  = (int)qf;
    float t  = fmaf(qf, -1.5707963705062866f, x);
    t = fmaf(qf, 4.3711388e-8f, t);
    float s = t * t;
    float c = fmaf(s, fmaf(s, fmaf(s, 2.4433157e-5f, -1.3887316e-3f), 4.1666646e-2f), -0.5f);
    c = fmaf(c, s, 1.0f);
    float sn = t * fmaf(s, fmaf(s, fmaf(s, -1.9515296e-4f, 8.3321609e-3f), -1.6666655e-1f), 1.0f);
    int qm = q & 3;
    return (qm == 0) ? c : (qm == 1) ? -sn : (qm == 2) ? -c : sn;
}

// ---- fused init ----
__global__ void k_init(const float* freq, const float* theta, const float* sigma,
                       const float* f0, const float* theta0, const float* fbs) {
    int idx = blockIdx.x * blockDim.x + threadIdx.x;
    if (idx >= NPX) return;
    {
        int k = idx / HH, n = idx % HH;
        int m = (k * n) % HH;
        float s, c;
        sincospif((float)m / 96.0f, &s, &c);
        d_Wf[idx] = make_float2(c, -s);
        d_Wb[idx] = make_float2(c * (1.0f / 192.0f), s * (1.0f / 192.0f));
    }
    {
        int u = idx / HH, v = idx % HH;
        int hs = (u >= 96) ? u - 96 : u + 96;
        int ws = (v >= 96) ? v - 96 : v + 96;
        float yy = -1.0f + hs * (2.0f / 191.0f);
        float xx = -1.0f + ws * (2.0f / 191.0f);
        float r  = sqrtf(xx * xx + yy * yy + 1e-6f);
        d_pix[0][idx] = logf(r);
        d_pix[1][idx] = atan2f(yy, xx);
        d_pix[2][idx] = r;
    }
    if (idx < 576) {
        float sg = sigma[idx], f0v = f0[idx], t0 = theta0[idx];
        float lf0 = logf(f0v);
        float dl  = logf(sg) - lf0;
        d_soiA[idx] = make_float4(lf0, 0.5f / (dl * dl), theta[idx], 0.5f / (t0 * t0));
        d_soiB[idx] = make_float2(freq[idx], 1.0f / (6.283185307179586f * sg * sg));
    }
    if (idx < 192) {
        d_band[idx * 2 + 0] = (int)floorf((fbs[idx * 2 + 0] + 1.0f) * 0.5f * 192.0f);
        d_band[idx * 2 + 1] = (int)floorf((fbs[idx * 2 + 1] + 1.0f) * 0.5f * 192.0f);
    }
}

// ---- per-channel union bounding box (quadrant coords) ----
__global__ void k_box() {
    int o = threadIdx.x;            // 64 threads
    int os = (o + 32) & 63;
    int bmin = QW, bmax = 0;
    for (int i = 0; i < 3; i++) {
        int lo = d_band[(os * 3 + i) * 2] - 96;
        int hi = d_band[(os * 3 + i) * 2 + 1] - 96;
        if (lo < 0) lo = 0;
        if (hi > lo) { bmin = min(bmin, lo); bmax = max(bmax, hi); }
    }
    if (bmax <= bmin) { bmin = 0; bmax = 0; }
    d_obox[o] = make_int2(bmin, bmax);
}

// ---- forward DFT rows: Hermitian-packed pairs, R=4 (R15 config) ----
__global__ __launch_bounds__(192) void k_fwd_rows(const float* x) {
    int k = blockIdx.x, h0 = blockIdx.y * 4, tid = threadIdx.x;
    __shared__ float2 xs[4][HH];
    const float* xa = x + (2 * k)     * NPX;
    const float* xb = x + (2 * k + 1) * NPX;
    for (int j = tid; j < 4 * HH; j += 192) {
        int idx = (h0 + j / HH) * HH + (j % HH);
        xs[j / HH][j % HH] = make_float2(xa[idx], xb[idx]);
    }
    __syncthreads();
    float ar[4], ai[4];
    #pragma unroll
    for (int r = 0; r < 4; r++) { ar[r] = 0.0f; ai[r] = 0.0f; }
    #pragma unroll 8
    for (int w = 0; w < HH; w++) {
        float2 W = d_Wf[w * HH + tid];
        #pragma unroll
        for (int r = 0; r < 4; r++) {
            float2 xv = xs[r][w];
            ar[r] = fmaf(xv.x, W.x, fmaf(-xv.y, W.y, ar[r]));
            ai[r] = fmaf(xv.x, W.y, fmaf( xv.y, W.x, ai[r]));
        }
    }
    #pragma unroll
    for (int r = 0; r < 4; r++)
        d_Y[k][(h0 + r) * HH + tid] = make_float2(ar[r], ai[r]);
}

// ---- forward DFT cols: 6 packed transforms, R=4 ----
__global__ __launch_bounds__(192) void k_fwd_cols() {
    int k = blockIdx.x, u0 = blockIdx.y * 4, tid = threadIdx.x;
    __shared__ float2 wt[4][HH];
    for (int j = tid; j < 4 * HH; j += 192)
        wt[j / HH][j % HH] = d_Wf[(u0 + j / HH) * HH + (j % HH)];
    __syncthreads();
    float fr[4], fi[4];
    #pragma unroll
    for (int r = 0; r < 4; r++) { fr[r] = 0.0f; fi[r] = 0.0f; }
    #pragma unroll 8
    for (int h = 0; h < HH; h++) {
        float2 y = d_Y[k][h * HH + tid];
        #pragma unroll
        for (int r = 0; r < 4; r++) {
            float2 w = wt[r][h];
            fr[r] = fmaf(w.x, y.x, fmaf(-w.y, y.y, fr[r]));
            fi[r] = fmaf(w.x, y.y, fmaf( w.y, y.x, fi[r]));
        }
    }
    #pragma unroll
    for (int r = 0; r < 4; r++)
        d_Z[k][(u0 + r) * HH + tid] = make_float2(fr[r], fi[r]);
}

// ---- Hermitian unpack: Z[k] -> F[2k], F[2k+1] ----
__global__ __launch_bounds__(256) void k_unpack() {
    int px = blockIdx.x * 256 + threadIdx.x;
    if (px >= NPX) return;
    int k = blockIdx.y;
    int u = px / HH, v = px % HH;
    int mu = (HH - u) % HH, mv = (HH - v) % HH;
    float2 Z  = d_Z[k][px];
    float2 Zm = d_Z[k][mu * HH + mv];
    d_F[2 * k    ][px] = make_float2(0.5f * (Z.x + Zm.x), 0.5f * (Z.y - Zm.y));
    d_F[2 * k + 1][px] = make_float2(0.5f * (Z.y + Zm.y), 0.5f * (Zm.x - Z.x));
}

// ---- attention stats: 128-px tiles, pixel-major h1, float4 Gram ----
__global__ __launch_bounds__(192) void k_attn_stats(const float* w1, const float* b1) {
    int b = blockIdx.x, py = blockIdx.y, px0 = py * 128, tid = threadIdx.x;
    __shared__ float mags[3][128];
    __shared__ __align__(16) float h1t[128][64];   // pixel-major
    for (int jj = tid; jj < 384; jj += 192) {
        int c = jj >> 7, p = jj & 127;
        int ip = (c == 0) ? 2 : (c - 1);           // channel fftshift perm
        float2 F = d_F[b * 3 + ip][px0 + p];
        mags[c][p] = sqrtf(F.x * F.x + F.y * F.y);
    }
    int hid = tid & 63, grp = tid >> 6;
    float w1a = w1[hid * 3], w1b = w1[hid * 3 + 1], w1c = w1[hid * 3 + 2], b1v = b1[hid];
    __syncthreads();
    for (int p = grp; p < 128; p += 3)
        h1t[p][hid] = fmaxf(fmaf(w1a, mags[0][p],
                       fmaf(w1b, mags[1][p], fmaf(w1c, mags[2][p], b1v))), 0.0f);
    __syncthreads();
    int blk = b * 288 + py;
    if (tid < 64) {
        float s = 0.0f;
        #pragma unroll 8
        for (int p = 0; p < 128; p++) s += h1t[p][tid];
        d_gpart[blk][NTILE * 16 + tid] = s;
    }
    if (tid < NTILE) {
        int J = 0, rem = tid;
        while (rem >= 16 - J) { rem -= 16 - J; J++; }
        int K = J + rem;
        float acc[4][4];
        #pragma unroll
        for (int a = 0; a < 4; a++)
            #pragma unroll
            for (int c = 0; c < 4; c++) acc[a][c] = 0.0f;
        #pragma unroll 4
        for (int p = 0; p < 128; p++) {
            float4 ra = *(const float4*)&h1t[p][J * 4];
            float4 rb = *(const float4*)&h1t[p][K * 4];
            acc[0][0] = fmaf(ra.x, rb.x, acc[0][0]);
            acc[0][1] = fmaf(ra.x, rb.y, acc[0][1]);
            acc[0][2] = fmaf(ra.x, rb.z, acc[0][2]);
            acc[0][3] = fmaf(ra.x, rb.w, acc[0][3]);
            acc[1][0] = fmaf(ra.y, rb.x, acc[1][0]);
            acc[1][1] = fmaf(ra.y, rb.y, acc[1][1]);
            acc[1][2] = fmaf(ra.y, rb.z, acc[1][2]);
            acc[1][3] = fmaf(ra.y, rb.w, acc[1][3]);
            acc[2][0] = fmaf(ra.z, rb.x, acc[2][0]);
            acc[2][1] = fmaf(ra.z, rb.y, acc[2][1]);
            acc[2][2] = fmaf(ra.z, rb.z, acc[2][2]);
            acc[2][3] = fmaf(ra.z, rb.w, acc[2][3]);
            acc[3][0] = fmaf(ra.w, rb.x, acc[3][0]);
            acc[3][1] = fmaf(ra.w, rb.y, acc[3][1]);
            acc[3][2] = fmaf(ra.w, rb.z, acc[3][2]);
            acc[3][3] = fmaf(ra.w, rb.w, acc[3][3]);
        }
        #pragma unroll
        for (int a = 0; a < 4; a++)
            #pragma unroll
            for (int c = 0; c < 4; c++)
                d_gpart[blk][tid * 16 + a * 4 + c] = acc[a][c];
    }
}

// ---- attention h2: 128-px quadrant tiles, padded h1 ----
__global__ __launch_bounds__(192) void k_attn_h2(const float* w1, const float* b1,
                                                 const float* w2, const float* b2) {
    int b = blockIdx.x, q0 = blockIdx.y * 128, tid = threadIdx.x;
    __shared__ float mags[3][128];
    __shared__ __align__(16) float h1s[64][132];   // hid-major, pad 132
    for (int jj = tid; jj < 384; jj += 192) {
        int c = jj >> 7, p = jj & 127;
        int q = q0 + p;
        int px = (q / QW) * HH + (q % QW);
        int ip = (c == 0) ? 2 : (c - 1);
        float2 F = d_F[b * 3 + ip][px];
        mags[c][p] = sqrtf(F.x * F.x + F.y * F.y);
    }
    int hid = tid & 63, grp = tid >> 6;
    float w1a = w1[hid * 3], w1b = w1[hid * 3 + 1], w1c = w1[hid * 3 + 2], b1v = b1[hid];
    __syncthreads();
    for (int p = grp; p < 128; p += 3)
        h1s[hid][p] = fmaxf(fmaf(w1a, mags[0][p],
                       fmaf(w1b, mags[1][p], fmaf(w1c, mags[2][p], b1v))), 0.0f);
    float w2row[64];
    #pragma unroll
    for (int j = 0; j < 64; j++) w2row[j] = w2[tid * 64 + j];
    float bias2 = b2[tid];
    __syncthreads();
    for (int g = 0; g < 32; g++) {
        float a0 = bias2, a1 = bias2, a2 = bias2, a3 = bias2;
        #pragma unroll
        for (int j = 0; j < 64; j++) {
            float4 h = *(const float4*)&h1s[j][g * 4];
            float wv = w2row[j];
            a0 = fmaf(wv, h.x, a0); a1 = fmaf(wv, h.y, a1);
            a2 = fmaf(wv, h.z, a2); a3 = fmaf(wv, h.w, a3);
        }
        long base = ((long)b * NQ + q0 + g * 4) * NCH + tid;
        d_h2q[base          ] = a0;
        d_h2q[base + NCH    ] = a1;
        d_h2q[base + 2 * NCH] = a2;
        d_h2q[base + 3 * NCH] = a3;
    }
}

// ---- Gram/S reduction ----
__global__ __launch_bounds__(256) void k_gred1() {
    int m = blockIdx.x;
    for (int e = threadIdx.x; e < GPW; e += 256) {
        double s = 0.0;
        for (int blk = m * 32; blk < m * 32 + 32; blk++)
            s += (double)d_gpart[blk][e];
        d_gmid[m][e] = s;
    }
}
__global__ __launch_bounds__(256) void k_gred2() {
    for (int e = threadIdx.x; e < GPW; e += 256) {
        double s = 0.0;
        for (int m = 0; m < 36; m++) s += d_gmid[m][e];
        if (e < NTILE * 16) d_Gd[e] = s;
        else d_Sd[e - NTILE * 16] = s;
    }
}

// ---- BN finalize via quadratic form ----
__global__ __launch_bounds__(64) void k_bnfin(const float* w2, const float* b2,
                                              const float* bnw, const float* bnb) {
    int c = blockIdx.x, j = threadIdx.x;
    __shared__ float w2s[64];
    __shared__ double sh1[64], sh2[64];
    w2s[j] = w2[c * 64 + j];
    __syncthreads();
    double wj = (double)w2s[j];
    double rowsum = 0.0;
    for (int k = 0; k < 64; k++) {
        int J = j >> 2, K = k >> 2, rj = j & 3, rk = k & 3;
        int off;
        if (J <= K) off = (J * 16 - (J * (J - 1)) / 2 + (K - J)) * 16 + rj * 4 + rk;
        else        off = (K * 16 - (K * (K - 1)) / 2 + (J - K)) * 16 + rk * 4 + rj;
        rowsum += d_Gd[off] * (double)w2s[k];
    }
    sh1[j] = wj * rowsum;
    sh2[j] = wj * d_Sd[j];
    __syncthreads();
    if (j == 0) {
        double quad = 0.0, ws = 0.0;
        for (int k = 0; k < 64; k++) { quad += sh1[k]; ws += sh2[k]; }
        double N   = (double)((long)NB * NPX);
        double b2c = (double)b2[c];
        double mu  = (ws + N * b2c) / N;
        double msq = (quad + 2.0 * b2c * ws + N * b2c * b2c) / N;
        double var = msq - mu * mu;
        float inv  = (float)(1.0 / sqrt(var + 1e-5));
        float A    = inv * bnw[c];
        d_bnA[c] = A;
        d_bnB[c] = bnb[c] - (float)mu * A;
    }
}

// ---- fused BN + softmax + gabor + A_tot: warp-per-pixel ----
__global__ __launch_bounds__(192) void k_atot() {
    int wid = threadIdx.x >> 5, lane = threadIdx.x & 31;
    int q = blockIdx.x * 6 + wid;
    int u = q / QW, v = q % QW;
    int px = u * HH + v;
    float2 Fv = make_float2(0.0f, 0.0f);
    if (lane < 12) {
        int b = lane / 3, i = lane % 3;
        int ip = (i == 0) ? 2 : (i - 1);
        Fv = d_F[b * 3 + ip][px];
    }
    float pv = (lane < 3) ? d_pix[lane][px] : 0.0f;
    float L   = __shfl_sync(0xffffffffu, pv, 0);
    float phi = __shfl_sync(0xffffffffu, pv, 1);
    float rr  = __shfl_sync(0xffffffffu, pv, 2);
    float Xr[4][3], Xi[4][3];
    #pragma unroll
    for (int b = 0; b < 4; b++)
        #pragma unroll
        for (int i = 0; i < 3; i++) {
            Xr[b][i] = __shfl_sync(0xffffffffu, Fv.x, b * 3 + i);
            Xi[b][i] = __shfl_sync(0xffffffffu, Fv.y, b * 3 + i);
        }
    float bnA[6], bnB[6];
    #pragma unroll
    for (int k = 0; k < 6; k++) {
        bnA[k] = d_bnA[lane + 32 * k];
        bnB[k] = d_bnB[lane + 32 * k];
    }
    float e[4][6], ssum[4];
    #pragma unroll
    for (int b = 0; b < 4; b++) {
        long base = ((long)b * NQ + q) * NCH + lane;
        float ls = 0.0f;
        #pragma unroll
        for (int k = 0; k < 6; k++) {
            e[b][k] = fexp(fmaf(d_h2q[base + 32 * k], bnA[k], bnB[k]));
            ls += e[b][k];
        }
        #pragma unroll
        for (int o = 16; o > 0; o >>= 1) ls += __shfl_xor_sync(0xffffffffu, ls, o);
        ssum[b] = ls;
    }
    float i0 = 1.0f / ssum[0], i1 = 1.0f / ssum[1], i2 = 1.0f / ssum[2], i3 = 1.0f / ssum[3];
    float accr = 0.0f, acci = 0.0f;
    #pragma unroll
    for (int k = 0; k < 6; k++) {
        int c = lane + 32 * k;
        float w0 = e[0][k] * i0, w1 = e[1][k] * i1, w2v = e[2][k] * i2, w3 = e[3][k] * i3;
        #pragma unroll
        for (int i = 0; i < 3; i++) {
            float ar = w0 * Xr[0][i] + w1 * Xr[1][i] + w2v * Xr[2][i] + w3 * Xr[3][i];
            float ai = w0 * Xi[0][i] + w1 * Xi[1][i] + w2v * Xi[2][i] + w3 * Xi[3][i];
            float4 pa = d_soiA[c * 3 + i];
            float2 pb = d_soiB[c * 3 + i];
            float dl = L - pa.x;
            float dp = phi - pa.z;
            float g = fexp(-(dl * dl) * pa.y - (dp * dp) * pa.w) * fcos(pb.x * rr) * pb.y;
            accr = fmaf(g, ar, accr);
            acci = fmaf(g, ai, acci);
        }
    }
    #pragma unroll
    for (int o = 16; o > 0; o >>= 1) {
        accr += __shfl_xor_sync(0xffffffffu, accr, o);
        acci += __shfl_xor_sync(0xffffffffu, acci, o);
    }
    if (lane == 0) d_A[q] = make_float2(accr, acci);
}

// ---- inverse DFT rows: R=12, static loops; zero-fill strips outside box ----
__global__ __launch_bounds__(192) void k_inv_rows() {
    int o = blockIdx.x, u0 = blockIdx.y * 12, tid = threadIdx.x;
    int2 box = d_obox[o];
    if (u0 >= box.y || u0 + 12 <= box.x) {
        float2 z = make_float2(0.0f, 0.0f);
        #pragma unroll
        for (int r = 0; r < 12; r++)
            d_T[o][(u0 + r) * HH + tid] = z;
        return;
    }
    int os = (o + 32) & 63;
    int lo0 = d_band[(os * 3 + 0) * 2] - 96, hi0 = d_band[(os * 3 + 0) * 2 + 1] - 96;
    int lo1 = d_band[(os * 3 + 1) * 2] - 96, hi1 = d_band[(os * 3 + 1) * 2 + 1] - 96;
    int lo2 = d_band[(os * 3 + 2) * 2] - 96, hi2 = d_band[(os * 3 + 2) * 2 + 1] - 96;
    __shared__ float2 qs[12][QW];
    for (int j = tid; j < 12 * QW; j += 192) {
        int r = j / QW, v = j % QW;
        int u = u0 + r;
        bool a0 = (u >= lo0) && (u < hi0), b0 = (v >= lo0) && (v < hi0);
        bool a1 = (u >= lo1) && (u < hi1), b1 = (v >= lo1) && (v < hi1);
        bool a2 = (u >= lo2) && (u < hi2), b2 = (v >= lo2) && (v < hi2);
        float m = (float)((a0 & b0) + (a1 & b1) + (a2 & b2));
        float2 a = d_A[u * QW + v];
        qs[r][v] = make_float2(a.x * m, a.y * m);
    }
    __syncthreads();
    float tr[12], ti[12];
    #pragma unroll
    for (int r = 0; r < 12; r++) { tr[r] = 0.0f; ti[r] = 0.0f; }
    #pragma unroll 8
    for (int v = 0; v < QW; v++) {
        float2 w = d_Wb[v * HH + tid];
        #pragma unroll
        for (int r = 0; r < 12; r++) {
            float2 qv = qs[r][v];
            tr[r] = fmaf(qv.x, w.x, fmaf(-qv.y, w.y, tr[r]));
            ti[r] = fmaf(qv.x, w.y, fmaf( qv.y, w.x, ti[r]));
        }
    }
    #pragma unroll
    for (int r = 0; r < 12; r++)
        d_T[o][(u0 + r) * HH + tid] = make_float2(tr[r], ti[r]);
}

// ---- inverse DFT cols (real part), R=12 ----
__global__ __launch_bounds__(192) void k_inv_cols() {
    int o = blockIdx.x, s0 = blockIdx.y * 12, tid = threadIdx.x;
    __shared__ float2 wt[12][QW];
    for (int j = tid; j < 12 * QW; j += 192) {
        int r = j / QW, u = j % QW;
        wt[r][u] = d_Wb[(s0 + r) * HH + u];
    }
    __syncthreads();
    float acc[12];
    #pragma unroll
    for (int r = 0; r < 12; r++) acc[r] = 0.0f;
    #pragma unroll 8
    for (int u = 0; u < QW; u++) {
        float2 t = d_T[o][u * HH + tid];
        #pragma unroll
        for (int r = 0; r < 12; r++) {
            float2 w = wt[r][u];
            acc[r] = fmaf(w.x, t.x, fmaf(-w.y, t.y, acc[r]));
        }
    }
    #pragma unroll
    for (int r = 0; r < 12; r++)
        d_xf[o * NPX + (s0 + r) * HH + tid] = acc[r];
}

// ---- 3x3 conv + mixing: 2-px per thread, STG.64 ----
__global__ __launch_bounds__(128) void k_conv(const float* x, const float* cw,
                                              const float* mp, float* out) {
    int b = blockIdx.z;
    int h0 = blockIdx.y * 16, w0 = blockIdx.x * 16;
    int tx = threadIdx.x, ty = threadIdx.y;      // tx 0..7, ty 0..15
    int t = ty * 8 + tx;                          // 128 threads
    __shared__ float xt[3][18][18];
    __shared__ __align__(16) float cws[64 * 28];
    for (int j = t; j < 972; j += 128) {
        int i = j / 324, rem = j % 324, hh = rem / 18, ww = rem % 18;
        int gh = h0 - 1 + hh, gw = w0 - 1 + ww;
        xt[i][hh][ww] = (gh >= 0 && gh < HH && gw >= 0 && gw < HH)
                        ? x[(b * 3 + i) * NPX + gh * HH + gw] : 0.0f;
    }
    for (int j = t; j < 1728; j += 128) cws[(j / 27) * 28 + (j % 27)] = cw[j];
    for (int j = t; j < 64; j += 128) cws[j * 28 + 27] = 0.0f;
    __syncthreads();
    float mix = mp[0];
    float win0[28], win1[28];
    #pragma unroll
    for (int i = 0; i < 3; i++)
        #pragma unroll
        for (int kh = 0; kh < 3; kh++)
            #pragma unroll
            for (int kw = 0; kw < 3; kw++) {
                win0[i * 9 + kh * 3 + kw] = xt[i][ty + kh][2 * tx + kw];
                win1[i * 9 + kh * 3 + kw] = xt[i][ty + kh][2 * tx + kw + 1];
            }
    win0[27] = 0.0f; win1[27] = 0.0f;
    int pix = (h0 + ty) * HH + (w0 + 2 * tx);
    for (int o = 0; o < 64; o++) {
        float a0 = 0.0f, a1 = 0.0f;
        #pragma unroll
        for (int g = 0; g < 7; g++) {
            float4 cv = *(const float4*)&cws[o * 28 + g * 4];
            a0 = fmaf(win0[g*4+0], cv.x, a0);
            a0 = fmaf(win0[g*4+1], cv.y, a0);
            a0 = fmaf(win0[g*4+2], cv.z, a0);
            a0 = fmaf(win0[g*4+3], cv.w, a0);
            a1 = fmaf(win1[g*4+0], cv.x, a1);
            a1 = fmaf(win1[g*4+1], cv.y, a1);
            a1 = fmaf(win1[g*4+2], cv.z, a1);
            a1 = fmaf(win1[g*4+3], cv.w, a1);
        }
        long obase = ((long)(b * 64 + o) * NPX) + pix;
        float2 xf = *(const float2*)&d_xf[o * NPX + pix];
        float2 res = make_float2(fmaf(mix, xf.x, (1.0f - mix) * a0),
                                 fmaf(mix, xf.y, (1.0f - mix) * a1));
        *(float2*)&out[obase] = res;
    }
}

extern "C" void kernel_launch(void* const* d_in, const int* in_sizes, int n_in,
                              void* d_out, int out_size) {
    const float* x    = (const float*)d_in[0];
    const float* freq = (const float*)d_in[1];
    const float* thet = (const float*)d_in[2];
    const float* sigm = (const float*)d_in[3];
    const float* f0   = (const float*)d_in[4];
    const float* th0  = (const float*)d_in[5];
    const float* w1   = (const float*)d_in[6];
    const float* b1   = (const float*)d_in[7];
    const float* w2   = (const float*)d_in[8];
    const float* b2   = (const float*)d_in[9];
    const float* bnw  = (const float*)d_in[10];
    const float* bnb  = (const float*)d_in[11];
    const float* mp   = (const float*)d_in[12];
    const float* cw   = (const float*)d_in[13];
    const float* fbs  = (const float*)d_in[14];
    float* out = (float*)d_out;

    k_init<<<144, 256>>>(freq, thet, sigm, f0, th0, fbs);
    k_box<<<1, 64>>>();
    k_fwd_rows<<<dim3(6, 48), 192>>>(x);
    k_fwd_cols<<<dim3(6, 48), 192>>>();
    k_unpack<<<dim3(144, 6), 256>>>();
    k_attn_stats<<<dim3(4, 288), 192>>>(w1, b1);
    k_attn_h2<<<dim3(4, 72), 192>>>(w1, b1, w2, b2);
    k_gred1<<<36, 256>>>();
    k_gred2<<<1, 256>>>();
    k_bnfin<<<192, 64>>>(w2, b2, bnw, bnb);
    k_atot<<<1536, 192>>>();
    k_inv_rows<<<dim3(64, 8), 192>>>();
    k_inv_cols<<<dim3(64, 16), 192>>>();
    k_conv<<<dim3(12, 12, 4), dim3(8, 16)>>>(x, cw, mp, out);
}